// round 13
// baseline (speedup 1.0000x reference)
#include <cuda_runtime.h>
#include <cuda_bf16.h>
#include <cstdint>

// DeformConv3d 'HW' (t-offset == 0 -> 2D bilinear at integer t).
// R13 = R12 (HMMA m16n8k16 bf16 hi/lo split, warp = 32 points, fused pre-pass)
// with a rotated depth-2 pipeline: gather(k+1)'s 16 LDG.128 are issued between
// sync(k) and mma(k), so each tap's gather latency is hidden under the
// previous tap's ldmatrix/MMA + this tap's cvt/STS. Valid taps are contiguous
// (kstart..kend), so one flat rolled loop: the pipeline never drains.

#define NB  2
#define NC  16
#define NT  8
#define NH  64
#define NW  64
#define NCO 16
#define NK  27
#define HW  (NH * NW)
#define THW (NT * HW)

#define FMA2(d, a, b) \
    asm("fma.rn.f32x2 %0, %1, %2, %0;" : "+l"(d) : "l"(a), "l"(b))
#define PACKB(d, s) \
    asm("mov.b64 %0, {%1, %1};" : "=l"(d) : "f"(s))
#define UNPACK2(lo, hi, s) \
    asm("mov.b64 {%0, %1}, %2;" : "=f"(lo), "=f"(hi) : "l"(s))

#define MMA16816(D, A, B) \
    asm volatile("mma.sync.aligned.m16n8k16.row.col.f32.bf16.bf16.f32 " \
        "{%0,%1,%2,%3}, {%4,%5,%6,%7}, {%8,%9}, {%0,%1,%2,%3};" \
        : "+f"((D)[0]), "+f"((D)[1]), "+f"((D)[2]), "+f"((D)[3]) \
        : "r"((A)[0]), "r"((A)[1]), "r"((A)[2]), "r"((A)[3]), \
          "r"((B).x), "r"((B).y))

#define LDM4(R, ADDR) \
    asm volatile("ldmatrix.sync.aligned.m8n8.x4.shared.b16 {%0,%1,%2,%3}, [%4];" \
        : "=r"((R)[0]), "=r"((R)[1]), "=r"((R)[2]), "=r"((R)[3]) : "r"(ADDR))

static __device__ __forceinline__ uint32_t smem_u32(const void* p) {
    uint32_t a;
    asm("{ .reg .u64 t; cvta.to.shared.u64 t, %1; cvt.u32.u64 %0, t; }"
        : "=r"(a) : "l"(p));
    return a;
}

// ---------------------------------------------------------------------------
// scratch
__device__ __align__(16) float g_x4[NB * NT * 4 * HW * 4]; // c4 channels-last x
__device__ __align__(16) uint2 g_bfrag[NK * 2 * 2 * 32];   // B mma fragments

// fused pre-pass: blocks < 1024 transpose x; blocks >= 1024 pack B fragments.
__global__ void prep_kernel(const float* __restrict__ x,
                            const float* __restrict__ wgt)
{
    if (blockIdx.x < 1024) {
        const int tid = blockIdx.x * 256 + threadIdx.x;   // 0..262143
        const int hw = tid & (HW - 1);
        const int g  = (tid >> 12) & 3;
        const int t  = (tid >> 14) & 7;
        const int b  = tid >> 17;
        float4 v;
        v.x = __ldg(&x[((b * NC + 4 * g + 0) * NT + t) * HW + hw]);
        v.y = __ldg(&x[((b * NC + 4 * g + 1) * NT + t) * HW + hw]);
        v.z = __ldg(&x[((b * NC + 4 * g + 2) * NT + t) * HW + hw]);
        v.w = __ldg(&x[((b * NC + 4 * g + 3) * NT + t) * HW + hw]);
        reinterpret_cast<float4*>(g_x4)[tid] = v;
    } else {
        // B fragment pack (verified R9): g_bfrag[tap][split][ntile][lane];
        // lane l: b.x = {B[2(l%4)][n], B[2(l%4)+1][n]}, b.y = {B[+8][n],
        // B[+9][n]}, n = nt*8 + l/4, B[c][co] = w[co][c][tap].
        const int i = (blockIdx.x - 1024) * 256 + threadIdx.x;
        if (i >= NK * 2 * 2 * 32) return;
        const int l  = i & 31;
        const int nt = (i >> 5) & 1;
        const int s  = (i >> 6) & 1;
        const int k  = i >> 7;
        const int n  = nt * 8 + (l >> 2);
        const int kp = (l & 3) * 2;
        __nv_bfloat16 e[4];
#pragma unroll
        for (int j = 0; j < 4; j++) {
            const int c = kp + (j & 1) + (j >> 1) * 8;
            const float v = wgt[(n * NC + c) * NK + k];
            const __nv_bfloat16 hi = __float2bfloat16(v);
            e[j] = s ? __float2bfloat16(v - __bfloat162float(hi)) : hi;
        }
        __nv_bfloat162 r0 = __halves2bfloat162(e[0], e[1]);
        __nv_bfloat162 r1 = __halves2bfloat162(e[2], e[3]);
        uint2 o;
        o.x = *reinterpret_cast<uint32_t*>(&r0);
        o.y = *reinterpret_cast<uint32_t*>(&r1);
        g_bfrag[i] = o;
    }
}

// ---------------------------------------------------------------------------
// per-tap gather + bilinear + bf16 hi/lo split (R9 body, unchanged math).
// pl/kh/kw derived from flat tap index k by the caller.
static __device__ __forceinline__ void gather_tap(
    const ulonglong2* __restrict__ x4all, const float* __restrict__ tb,
    int k, int t, int h, int w,
    uint32_t hi[8], uint32_t lo[8])
{
    const int kt = k / 9;
    const int kr = k - kt * 9;
    const int kh = kr / 3;
    const int kw = kr - kh * 3;
    const ulonglong2* __restrict__ pl = x4all + (t - 1 + kt) * 4 * HW;

    const float offh = __ldg(tb + (2 * k) * THW);
    const float offw = __ldg(tb + (2 * k + 1) * THW);

    const float ph = (float)(h - 1 + kh) + offh;
    const float pw = (float)(w - 1 + kw) + offw;
    const int h0 = __float2int_rd(ph);
    const int w0 = __float2int_rd(pw);
    const float fh = ph - (float)h0;
    const float fw = pw - (float)w0;
    const int h1 = h0 + 1, w1 = w0 + 1;
    const bool vh0 = (h0 >= 0) & (h0 < NH);
    const bool vh1 = (h1 >= 0) & (h1 < NH);
    const bool vw0 = (w0 >= 0) & (w0 < NW);
    const bool vw1 = (w1 >= 0) & (w1 < NW);
    const float gh0 = 1.0f - fh, gw0 = 1.0f - fw;
    const float c00 = (vh0 & vw0) ? gh0 * gw0 : 0.0f;
    const float c01 = (vh0 & vw1) ? gh0 * fw  : 0.0f;
    const float c10 = (vh1 & vw0) ? fh  * gw0 : 0.0f;
    const float c11 = (vh1 & vw1) ? fh  * fw  : 0.0f;
    const int h0c = min(max(h0, 0), NH - 1);
    const int h1c = min(max(h1, 0), NH - 1);
    const int w0c = min(max(w0, 0), NW - 1);
    const int w1c = min(max(w1, 0), NW - 1);
    const int i00 = h0c * NW + w0c;
    const int i01 = h0c * NW + w1c;
    const int i10 = h1c * NW + w0c;
    const int i11 = h1c * NW + w1c;

    unsigned long long cc00, cc01, cc10, cc11;
    PACKB(cc00, c00); PACKB(cc01, c01);
    PACKB(cc10, c10); PACKB(cc11, c11);

#pragma unroll
    for (int g = 0; g < 4; g++) {
        const ulonglong2* __restrict__ pg = pl + g * HW;
        unsigned long long u0 = 0ULL, u1 = 0ULL;
        { const ulonglong2 a = __ldg(pg + i00);
          FMA2(u0, cc00, a.x); FMA2(u1, cc00, a.y); }
        { const ulonglong2 a = __ldg(pg + i01);
          FMA2(u0, cc01, a.x); FMA2(u1, cc01, a.y); }
        { const ulonglong2 a = __ldg(pg + i10);
          FMA2(u0, cc10, a.x); FMA2(u1, cc10, a.y); }
        { const ulonglong2 a = __ldg(pg + i11);
          FMA2(u0, cc11, a.x); FMA2(u1, cc11, a.y); }
        float v0, v1, v2, v3;
        UNPACK2(v0, v1, u0);
        UNPACK2(v2, v3, u1);
        __nv_bfloat162 hA = __floats2bfloat162_rn(v0, v1); // .x = even c
        __nv_bfloat162 hB = __floats2bfloat162_rn(v2, v3);
        float2 fA = __bfloat1622float2(hA);
        float2 fB = __bfloat1622float2(hB);
        __nv_bfloat162 lA = __floats2bfloat162_rn(v0 - fA.x, v1 - fA.y);
        __nv_bfloat162 lB = __floats2bfloat162_rn(v2 - fB.x, v3 - fB.y);
        hi[2 * g]     = *reinterpret_cast<uint32_t*>(&hA);
        hi[2 * g + 1] = *reinterpret_cast<uint32_t*>(&hB);
        lo[2 * g]     = *reinterpret_cast<uint32_t*>(&lA);
        lo[2 * g + 1] = *reinterpret_cast<uint32_t*>(&lB);
    }
}

static __device__ __forceinline__ void sts_tap(
    uint32_t abuf, int lane, const uint32_t hi[8], const uint32_t lo[8])
{
    const uint32_t r = abuf + (uint32_t)lane * 80;
    asm volatile("st.shared.v4.b32 [%0], {%1,%2,%3,%4};"
        :: "r"(r), "r"(hi[0]), "r"(hi[1]), "r"(hi[2]), "r"(hi[3]) : "memory");
    asm volatile("st.shared.v4.b32 [%0], {%1,%2,%3,%4};"
        :: "r"(r + 16), "r"(hi[4]), "r"(hi[5]), "r"(hi[6]), "r"(hi[7]) : "memory");
    asm volatile("st.shared.v4.b32 [%0], {%1,%2,%3,%4};"
        :: "r"(r + 32), "r"(lo[0]), "r"(lo[1]), "r"(lo[2]), "r"(lo[3]) : "memory");
    asm volatile("st.shared.v4.b32 [%0], {%1,%2,%3,%4};"
        :: "r"(r + 48), "r"(lo[4]), "r"(lo[5]), "r"(lo[6]), "r"(lo[7]) : "memory");
}

static __device__ __forceinline__ void mma_tap(
    uint32_t abuf, const uint2* __restrict__ bsm, int k, int lane,
    float d[2][2][4])
{
    uint32_t ah[2][4], al[2][4];
    const uint32_t r0a = abuf + (uint32_t)(lane & 15) * 80
                       + (uint32_t)(lane >> 4) * 16;
    LDM4(ah[0], r0a);
    LDM4(ah[1], r0a + 16 * 80);
    LDM4(al[0], r0a + 32);
    LDM4(al[1], r0a + 16 * 80 + 32);

    const uint2* __restrict__ bp = bsm + k * 128 + lane;
    const uint2 bh0 = bp[0];
    const uint2 bh1 = bp[32];
    const uint2 bl0 = bp[64];
    const uint2 bl1 = bp[96];

    MMA16816(d[0][0], ah[0], bh0); MMA16816(d[0][1], ah[0], bh1);
    MMA16816(d[1][0], ah[1], bh0); MMA16816(d[1][1], ah[1], bh1);
    MMA16816(d[0][0], al[0], bh0); MMA16816(d[0][1], al[0], bh1);
    MMA16816(d[1][0], al[1], bh0); MMA16816(d[1][1], al[1], bh1);
    MMA16816(d[0][0], ah[0], bl0); MMA16816(d[0][1], ah[0], bl1);
    MMA16816(d[1][0], ah[1], bl0); MMA16816(d[1][1], ah[1], bl1);
}

// ---------------------------------------------------------------------------
// main kernel: 256 threads = 8 warps, warp = 32 consecutive points.
// dynamic smem: B fragments, then per-warp double staging buffers.
#define BSM_BYTES   27648
#define STG_BYTES   2560
#define SMEM_BYTES  (BSM_BYTES + 8 * 2 * STG_BYTES)   // 68608

__global__ void __launch_bounds__(256, 2)
deform_conv3d_mma_kernel(const float* __restrict__ temp,
                         const float* __restrict__ bias,
                         float* __restrict__ out)
{
    extern __shared__ __align__(16) uint8_t dynsm[];
    uint2* bsm = reinterpret_cast<uint2*>(dynsm);

    const int tid = threadIdx.x;
    for (int i = tid; i < (NK * 2 * 2 * 32) / 2; i += 256)
        reinterpret_cast<uint4*>(bsm)[i] =
            reinterpret_cast<const uint4*>(g_bfrag)[i];
    __syncthreads();

    const int lane = tid & 31;
    const int wid  = tid >> 5;
    const int wpt  = blockIdx.x * 256 + wid * 32;  // warp base point
    const int pt   = wpt + lane;
    const int w = pt & 63;
    const int h = (pt >> 6) & 63;
    const int t = (pt >> 12) & 7;   // warp-uniform
    const int b = pt >> 15;         // warp-uniform
    const int sp = pt & (THW - 1);

    const uint32_t abuf0 = smem_u32(dynsm + BSM_BYTES + wid * 2 * STG_BYTES);
    const uint32_t abuf1 = abuf0 + STG_BYTES;
    const float* __restrict__ tb = temp + b * (2 * NK * THW) + sp;
    const ulonglong2* __restrict__ x4all =
        reinterpret_cast<const ulonglong2*>(g_x4) + b * NT * 4 * HW;

    float d[2][2][4];
#pragma unroll
    for (int m = 0; m < 2; m++)
#pragma unroll
        for (int n = 0; n < 2; n++)
#pragma unroll
            for (int j = 0; j < 4; j++) d[m][n][j] = 0.0f;

    // valid taps are contiguous: planes kt with 0 <= t-1+kt < NT
    const int kstart = (t == 0) ? 9 : 0;
    const int kend   = (t == NT - 1) ? 18 : NK;

    // rotated depth-2 pipeline:
    //   sts(k) ; syncwarp ; gather(k+1) [loads in flight] ; mma(k)
    uint32_t hi0[8], lo0[8], hi1[8], lo1[8];
    gather_tap(x4all, tb, kstart, t, h, w, hi0, lo0);

    int k = kstart;
    while (true) {
        // even step: staged set 0 -> abuf0
        sts_tap(abuf0, lane, hi0, lo0);
        __syncwarp();
        if (k + 1 < kend)
            gather_tap(x4all, tb, k + 1, t, h, w, hi1, lo1);
        mma_tap(abuf0, bsm, k, lane, d);
        k++;
        if (k >= kend) break;

        // odd step: staged set 1 -> abuf1
        sts_tap(abuf1, lane, hi1, lo1);
        __syncwarp();
        if (k + 1 < kend)
            gather_tap(x4all, tb, k + 1, t, h, w, hi0, lo0);
        mma_tap(abuf1, bsm, k, lane, d);
        k++;
        if (k >= kend) break;
    }

    // epilogue: D frag (m16n8): lane -> rows {l/4, l/4+8}, cols {2(l%4), +1}
    const int r0 = lane >> 2;
    const int cp = (lane & 3) * 2;
    const float bv[4] = { __ldg(bias + cp),     __ldg(bias + cp + 1),
                          __ldg(bias + cp + 8), __ldg(bias + cp + 9) };
    const int wsp = wpt & (THW - 1);
    float* __restrict__ ob = out + b * (NCO * THW) + wsp;
#pragma unroll
    for (int m = 0; m < 2; m++)
#pragma unroll
        for (int n = 0; n < 2; n++) {
            const int col = n * 8 + cp;
            const int row = 16 * m + r0;
            ob[(col)     * THW + row]     = d[m][n][0] + bv[n * 2 + 0];
            ob[(col + 1) * THW + row]     = d[m][n][1] + bv[n * 2 + 1];
            ob[(col)     * THW + row + 8] = d[m][n][2] + bv[n * 2 + 0];
            ob[(col + 1) * THW + row + 8] = d[m][n][3] + bv[n * 2 + 1];
        }
}

extern "C" void kernel_launch(void* const* d_in, const int* in_sizes, int n_in,
                              void* d_out, int out_size)
{
    const float* x    = (const float*)d_in[0];
    const float* temp = (const float*)d_in[1];
    const float* wgt  = (const float*)d_in[2];
    const float* bias = (const float*)d_in[3];
    float* out = (float*)d_out;

    cudaFuncSetAttribute(deform_conv3d_mma_kernel,
                         cudaFuncAttributeMaxDynamicSharedMemorySize,
                         SMEM_BYTES);

    prep_kernel<<<1024 + 14, 256>>>(x, wgt);
    deform_conv3d_mma_kernel<<<(NB * THW) / 256, 256, SMEM_BYTES>>>(
        temp, bias, out);
}

// round 14
// speedup vs baseline: 1.0353x; 1.0353x over previous
#include <cuda_runtime.h>
#include <cuda_bf16.h>
#include <cstdint>

// DeformConv3d 'HW' (t-offset == 0 -> 2D bilinear at integer t).
// R14 = R12 (HMMA m16n8k16 bf16 hi/lo split, warp = 32 points, fused pre-pass,
// unrolled plane loops) + tap-granularity rotated pipeline INSIDE the unrolled
// structure: per tap k: sts(k); syncwarp; gather(k+1); mma(k). Compile-time
// kh/kw (no div/mod), two staging register sets, drains only at the 2 plane
// boundaries.

#define NB  2
#define NC  16
#define NT  8
#define NH  64
#define NW  64
#define NCO 16
#define NK  27
#define HW  (NH * NW)
#define THW (NT * HW)

#define FMA2(d, a, b) \
    asm("fma.rn.f32x2 %0, %1, %2, %0;" : "+l"(d) : "l"(a), "l"(b))
#define PACKB(d, s) \
    asm("mov.b64 %0, {%1, %1};" : "=l"(d) : "f"(s))
#define UNPACK2(lo, hi, s) \
    asm("mov.b64 {%0, %1}, %2;" : "=f"(lo), "=f"(hi) : "l"(s))

#define MMA16816(D, A, B) \
    asm volatile("mma.sync.aligned.m16n8k16.row.col.f32.bf16.bf16.f32 " \
        "{%0,%1,%2,%3}, {%4,%5,%6,%7}, {%8,%9}, {%0,%1,%2,%3};" \
        : "+f"((D)[0]), "+f"((D)[1]), "+f"((D)[2]), "+f"((D)[3]) \
        : "r"((A)[0]), "r"((A)[1]), "r"((A)[2]), "r"((A)[3]), \
          "r"((B).x), "r"((B).y))

#define LDM4(R, ADDR) \
    asm volatile("ldmatrix.sync.aligned.m8n8.x4.shared.b16 {%0,%1,%2,%3}, [%4];" \
        : "=r"((R)[0]), "=r"((R)[1]), "=r"((R)[2]), "=r"((R)[3]) : "r"(ADDR))

static __device__ __forceinline__ uint32_t smem_u32(const void* p) {
    uint32_t a;
    asm("{ .reg .u64 t; cvta.to.shared.u64 t, %1; cvt.u32.u64 %0, t; }"
        : "=r"(a) : "l"(p));
    return a;
}

// ---------------------------------------------------------------------------
// scratch
__device__ __align__(16) float g_x4[NB * NT * 4 * HW * 4]; // c4 channels-last x
__device__ __align__(16) uint2 g_bfrag[NK * 2 * 2 * 32];   // B mma fragments

// fused pre-pass: blocks < 1024 transpose x; blocks >= 1024 pack B fragments.
__global__ void prep_kernel(const float* __restrict__ x,
                            const float* __restrict__ wgt)
{
    if (blockIdx.x < 1024) {
        const int tid = blockIdx.x * 256 + threadIdx.x;   // 0..262143
        const int hw = tid & (HW - 1);
        const int g  = (tid >> 12) & 3;
        const int t  = (tid >> 14) & 7;
        const int b  = tid >> 17;
        float4 v;
        v.x = __ldg(&x[((b * NC + 4 * g + 0) * NT + t) * HW + hw]);
        v.y = __ldg(&x[((b * NC + 4 * g + 1) * NT + t) * HW + hw]);
        v.z = __ldg(&x[((b * NC + 4 * g + 2) * NT + t) * HW + hw]);
        v.w = __ldg(&x[((b * NC + 4 * g + 3) * NT + t) * HW + hw]);
        reinterpret_cast<float4*>(g_x4)[tid] = v;
    } else {
        // B fragment pack (verified R9): g_bfrag[tap][split][ntile][lane];
        // lane l: b.x = {B[2(l%4)][n], B[2(l%4)+1][n]}, b.y = {B[+8][n],
        // B[+9][n]}, n = nt*8 + l/4, B[c][co] = w[co][c][tap].
        const int i = (blockIdx.x - 1024) * 256 + threadIdx.x;
        if (i >= NK * 2 * 2 * 32) return;
        const int l  = i & 31;
        const int nt = (i >> 5) & 1;
        const int s  = (i >> 6) & 1;
        const int k  = i >> 7;
        const int n  = nt * 8 + (l >> 2);
        const int kp = (l & 3) * 2;
        __nv_bfloat16 e[4];
#pragma unroll
        for (int j = 0; j < 4; j++) {
            const int c = kp + (j & 1) + (j >> 1) * 8;
            const float v = wgt[(n * NC + c) * NK + k];
            const __nv_bfloat16 hi = __float2bfloat16(v);
            e[j] = s ? __float2bfloat16(v - __bfloat162float(hi)) : hi;
        }
        __nv_bfloat162 r0 = __halves2bfloat162(e[0], e[1]);
        __nv_bfloat162 r1 = __halves2bfloat162(e[2], e[3]);
        uint2 o;
        o.x = *reinterpret_cast<uint32_t*>(&r0);
        o.y = *reinterpret_cast<uint32_t*>(&r1);
        g_bfrag[i] = o;
    }
}

// ---------------------------------------------------------------------------
// per-tap gather + bilinear + bf16 hi/lo split (R9 body, unchanged math)
static __device__ __forceinline__ void gather_tap(
    const ulonglong2* __restrict__ pl, const float* __restrict__ tb,
    int k, int kh, int kw, int h, int w,
    uint32_t hi[8], uint32_t lo[8])
{
    const float offh = __ldg(tb + (2 * k) * THW);
    const float offw = __ldg(tb + (2 * k + 1) * THW);

    const float ph = (float)(h - 1 + kh) + offh;
    const float pw = (float)(w - 1 + kw) + offw;
    const int h0 = __float2int_rd(ph);
    const int w0 = __float2int_rd(pw);
    const float fh = ph - (float)h0;
    const float fw = pw - (float)w0;
    const int h1 = h0 + 1, w1 = w0 + 1;
    const bool vh0 = (h0 >= 0) & (h0 < NH);
    const bool vh1 = (h1 >= 0) & (h1 < NH);
    const bool vw0 = (w0 >= 0) & (w0 < NW);
    const bool vw1 = (w1 >= 0) & (w1 < NW);
    const float gh0 = 1.0f - fh, gw0 = 1.0f - fw;
    const float c00 = (vh0 & vw0) ? gh0 * gw0 : 0.0f;
    const float c01 = (vh0 & vw1) ? gh0 * fw  : 0.0f;
    const float c10 = (vh1 & vw0) ? fh  * gw0 : 0.0f;
    const float c11 = (vh1 & vw1) ? fh  * fw  : 0.0f;
    const int h0c = min(max(h0, 0), NH - 1);
    const int h1c = min(max(h1, 0), NH - 1);
    const int w0c = min(max(w0, 0), NW - 1);
    const int w1c = min(max(w1, 0), NW - 1);
    const int i00 = h0c * NW + w0c;
    const int i01 = h0c * NW + w1c;
    const int i10 = h1c * NW + w0c;
    const int i11 = h1c * NW + w1c;

    unsigned long long cc00, cc01, cc10, cc11;
    PACKB(cc00, c00); PACKB(cc01, c01);
    PACKB(cc10, c10); PACKB(cc11, c11);

#pragma unroll
    for (int g = 0; g < 4; g++) {
        const ulonglong2* __restrict__ pg = pl + g * HW;
        unsigned long long u0 = 0ULL, u1 = 0ULL;
        { const ulonglong2 a = __ldg(pg + i00);
          FMA2(u0, cc00, a.x); FMA2(u1, cc00, a.y); }
        { const ulonglong2 a = __ldg(pg + i01);
          FMA2(u0, cc01, a.x); FMA2(u1, cc01, a.y); }
        { const ulonglong2 a = __ldg(pg + i10);
          FMA2(u0, cc10, a.x); FMA2(u1, cc10, a.y); }
        { const ulonglong2 a = __ldg(pg + i11);
          FMA2(u0, cc11, a.x); FMA2(u1, cc11, a.y); }
        float v0, v1, v2, v3;
        UNPACK2(v0, v1, u0);
        UNPACK2(v2, v3, u1);
        __nv_bfloat162 hA = __floats2bfloat162_rn(v0, v1); // .x = even c
        __nv_bfloat162 hB = __floats2bfloat162_rn(v2, v3);
        float2 fA = __bfloat1622float2(hA);
        float2 fB = __bfloat1622float2(hB);
        __nv_bfloat162 lA = __floats2bfloat162_rn(v0 - fA.x, v1 - fA.y);
        __nv_bfloat162 lB = __floats2bfloat162_rn(v2 - fB.x, v3 - fB.y);
        hi[2 * g]     = *reinterpret_cast<uint32_t*>(&hA);
        hi[2 * g + 1] = *reinterpret_cast<uint32_t*>(&hB);
        lo[2 * g]     = *reinterpret_cast<uint32_t*>(&lA);
        lo[2 * g + 1] = *reinterpret_cast<uint32_t*>(&lB);
    }
}

static __device__ __forceinline__ void sts_tap(
    uint32_t abuf, int lane, const uint32_t hi[8], const uint32_t lo[8])
{
    const uint32_t r = abuf + (uint32_t)lane * 80;
    asm volatile("st.shared.v4.b32 [%0], {%1,%2,%3,%4};"
        :: "r"(r), "r"(hi[0]), "r"(hi[1]), "r"(hi[2]), "r"(hi[3]) : "memory");
    asm volatile("st.shared.v4.b32 [%0], {%1,%2,%3,%4};"
        :: "r"(r + 16), "r"(hi[4]), "r"(hi[5]), "r"(hi[6]), "r"(hi[7]) : "memory");
    asm volatile("st.shared.v4.b32 [%0], {%1,%2,%3,%4};"
        :: "r"(r + 32), "r"(lo[0]), "r"(lo[1]), "r"(lo[2]), "r"(lo[3]) : "memory");
    asm volatile("st.shared.v4.b32 [%0], {%1,%2,%3,%4};"
        :: "r"(r + 48), "r"(lo[4]), "r"(lo[5]), "r"(lo[6]), "r"(lo[7]) : "memory");
}

static __device__ __forceinline__ void mma_tap(
    uint32_t abuf, const uint2* __restrict__ bsm, int k, int lane,
    float d[2][2][4])
{
    uint32_t ah[2][4], al[2][4];
    const uint32_t r0a = abuf + (uint32_t)(lane & 15) * 80
                       + (uint32_t)(lane >> 4) * 16;
    LDM4(ah[0], r0a);
    LDM4(ah[1], r0a + 16 * 80);
    LDM4(al[0], r0a + 32);
    LDM4(al[1], r0a + 16 * 80 + 32);

    const uint2* __restrict__ bp = bsm + k * 128 + lane;
    const uint2 bh0 = bp[0];
    const uint2 bh1 = bp[32];
    const uint2 bl0 = bp[64];
    const uint2 bl1 = bp[96];

    MMA16816(d[0][0], ah[0], bh0); MMA16816(d[0][1], ah[0], bh1);
    MMA16816(d[1][0], ah[1], bh0); MMA16816(d[1][1], ah[1], bh1);
    MMA16816(d[0][0], al[0], bh0); MMA16816(d[0][1], al[0], bh1);
    MMA16816(d[1][0], al[1], bh0); MMA16816(d[1][1], al[1], bh1);
    MMA16816(d[0][0], ah[0], bl0); MMA16816(d[0][1], ah[0], bl1);
    MMA16816(d[1][0], ah[1], bl0); MMA16816(d[1][1], ah[1], bl1);
}

// ---------------------------------------------------------------------------
// main kernel: 256 threads = 8 warps, warp = 32 consecutive points.
// dynamic smem: B fragments, then per-warp double staging buffers.
#define BSM_BYTES   27648
#define STG_BYTES   2560
#define SMEM_BYTES  (BSM_BYTES + 8 * 2 * STG_BYTES)   // 68608

__global__ void __launch_bounds__(256, 2)
deform_conv3d_mma_kernel(const float* __restrict__ temp,
                         const float* __restrict__ bias,
                         float* __restrict__ out)
{
    extern __shared__ __align__(16) uint8_t dynsm[];
    uint2* bsm = reinterpret_cast<uint2*>(dynsm);

    const int tid = threadIdx.x;
    for (int i = tid; i < (NK * 2 * 2 * 32) / 2; i += 256)
        reinterpret_cast<uint4*>(bsm)[i] =
            reinterpret_cast<const uint4*>(g_bfrag)[i];
    __syncthreads();

    const int lane = tid & 31;
    const int wid  = tid >> 5;
    const int wpt  = blockIdx.x * 256 + wid * 32;  // warp base point
    const int pt   = wpt + lane;
    const int w = pt & 63;
    const int h = (pt >> 6) & 63;
    const int t = (pt >> 12) & 7;   // warp-uniform
    const int b = pt >> 15;         // warp-uniform
    const int sp = pt & (THW - 1);

    const uint32_t abuf0 = smem_u32(dynsm + BSM_BYTES + wid * 2 * STG_BYTES);
    const uint32_t abuf1 = abuf0 + STG_BYTES;
    const float* __restrict__ tb = temp + b * (2 * NK * THW) + sp;
    const ulonglong2* __restrict__ x4all =
        reinterpret_cast<const ulonglong2*>(g_x4) + b * NT * 4 * HW;

    float d[2][2][4];
#pragma unroll
    for (int m = 0; m < 2; m++)
#pragma unroll
        for (int n = 0; n < 2; n++)
#pragma unroll
            for (int j = 0; j < 4; j++) d[m][n][j] = 0.0f;

    uint32_t hi0[8], lo0[8], hi1[8], lo1[8];

    for (int kt = 0; kt < 3; kt++) {
        const int ti = t - 1 + kt;
        if (ti < 0 || ti >= NT) continue;            // warp-uniform branch
        const ulonglong2* __restrict__ pl = x4all + ti * 4 * HW;
        const int kb = kt * 9;

        // rotated depth-2 pipeline within the unrolled plane:
        //   sts(k) ; syncwarp ; gather(k+1) ; mma(k)
        gather_tap(pl, tb, kb + 0, 0, 0, h, w, hi0, lo0);

#pragma unroll
        for (int kk = 0; kk < 9; kk++) {
            const uint32_t abuf = (kk & 1) ? abuf1 : abuf0;
            if (kk & 1) sts_tap(abuf, lane, hi1, lo1);
            else        sts_tap(abuf, lane, hi0, lo0);
            __syncwarp();
            if (kk < 8) {
                const int kn  = kk + 1;
                const int khn = kn / 3;       // compile-time (kk unrolled)
                const int kwn = kn - khn * 3;
                if (kk & 1) gather_tap(pl, tb, kb + kn, khn, kwn, h, w, hi0, lo0);
                else        gather_tap(pl, tb, kb + kn, khn, kwn, h, w, hi1, lo1);
            }
            mma_tap(abuf, bsm, kb + kk, lane, d);
        }
        __syncwarp();   // WAR: next plane's first sts vs this plane's ldmatrix
    }

    // epilogue: D frag (m16n8): lane -> rows {l/4, l/4+8}, cols {2(l%4), +1}
    const int r0 = lane >> 2;
    const int cp = (lane & 3) * 2;
    const float bv[4] = { __ldg(bias + cp),     __ldg(bias + cp + 1),
                          __ldg(bias + cp + 8), __ldg(bias + cp + 9) };
    const int wsp = wpt & (THW - 1);
    float* __restrict__ ob = out + b * (NCO * THW) + wsp;
#pragma unroll
    for (int m = 0; m < 2; m++)
#pragma unroll
        for (int n = 0; n < 2; n++) {
            const int col = n * 8 + cp;
            const int row = 16 * m + r0;
            ob[(col)     * THW + row]     = d[m][n][0] + bv[n * 2 + 0];
            ob[(col + 1) * THW + row]     = d[m][n][1] + bv[n * 2 + 1];
            ob[(col)     * THW + row + 8] = d[m][n][2] + bv[n * 2 + 0];
            ob[(col + 1) * THW + row + 8] = d[m][n][3] + bv[n * 2 + 1];
        }
}

extern "C" void kernel_launch(void* const* d_in, const int* in_sizes, int n_in,
                              void* d_out, int out_size)
{
    const float* x    = (const float*)d_in[0];
    const float* temp = (const float*)d_in[1];
    const float* wgt  = (const float*)d_in[2];
    const float* bias = (const float*)d_in[3];
    float* out = (float*)d_out;

    cudaFuncSetAttribute(deform_conv3d_mma_kernel,
                         cudaFuncAttributeMaxDynamicSharedMemorySize,
                         SMEM_BYTES);

    prep_kernel<<<1024 + 14, 256>>>(x, wgt);
    deform_conv3d_mma_kernel<<<(NB * THW) / 256, 256, SMEM_BYTES>>>(
        temp, bias, out);
}

// round 15
// speedup vs baseline: 1.1265x; 1.0881x over previous
#include <cuda_runtime.h>
#include <cuda_bf16.h>
#include <cstdint>

// DeformConv3d 'HW' (t-offset == 0 -> 2D bilinear at integer t).
// R15 = R12 tap body (HMMA m16n8k16 bf16 hi/lo split, warp = 32 points,
// pair-pipelined staging) re-granularized to ONE WARP PER BLOCK:
//  - grid 2048 x 32 threads, 16 blocks/SM -> near-perfect SM load balance
//    (14 vs 13.84 warp-units per SM, was 16 vs 13.84)
//  - B fragments read directly from global (L1-resident 27.6KB table):
//    no per-block smem copy, no __syncthreads at all

#define NB  2
#define NC  16
#define NT  8
#define NH  64
#define NW  64
#define NCO 16
#define NK  27
#define HW  (NH * NW)
#define THW (NT * HW)

#define FMA2(d, a, b) \
    asm("fma.rn.f32x2 %0, %1, %2, %0;" : "+l"(d) : "l"(a), "l"(b))
#define PACKB(d, s) \
    asm("mov.b64 %0, {%1, %1};" : "=l"(d) : "f"(s))
#define UNPACK2(lo, hi, s) \
    asm("mov.b64 {%0, %1}, %2;" : "=f"(lo), "=f"(hi) : "l"(s))

#define MMA16816(D, A, B) \
    asm volatile("mma.sync.aligned.m16n8k16.row.col.f32.bf16.bf16.f32 " \
        "{%0,%1,%2,%3}, {%4,%5,%6,%7}, {%8,%9}, {%0,%1,%2,%3};" \
        : "+f"((D)[0]), "+f"((D)[1]), "+f"((D)[2]), "+f"((D)[3]) \
        : "r"((A)[0]), "r"((A)[1]), "r"((A)[2]), "r"((A)[3]), \
          "r"((B).x), "r"((B).y))

#define LDM4(R, ADDR) \
    asm volatile("ldmatrix.sync.aligned.m8n8.x4.shared.b16 {%0,%1,%2,%3}, [%4];" \
        : "=r"((R)[0]), "=r"((R)[1]), "=r"((R)[2]), "=r"((R)[3]) : "r"(ADDR))

static __device__ __forceinline__ uint32_t smem_u32(const void* p) {
    uint32_t a;
    asm("{ .reg .u64 t; cvta.to.shared.u64 t, %1; cvt.u32.u64 %0, t; }"
        : "=r"(a) : "l"(p));
    return a;
}

// ---------------------------------------------------------------------------
// scratch
__device__ __align__(16) float g_x4[NB * NT * 4 * HW * 4]; // c4 channels-last x
__device__ __align__(16) uint2 g_bfrag[NK * 2 * 2 * 32];   // B mma fragments

// fused pre-pass: blocks < 1024 transpose x; blocks >= 1024 pack B fragments.
__global__ void prep_kernel(const float* __restrict__ x,
                            const float* __restrict__ wgt)
{
    if (blockIdx.x < 1024) {
        const int tid = blockIdx.x * 256 + threadIdx.x;   // 0..262143
        const int hw = tid & (HW - 1);
        const int g  = (tid >> 12) & 3;
        const int t  = (tid >> 14) & 7;
        const int b  = tid >> 17;
        float4 v;
        v.x = __ldg(&x[((b * NC + 4 * g + 0) * NT + t) * HW + hw]);
        v.y = __ldg(&x[((b * NC + 4 * g + 1) * NT + t) * HW + hw]);
        v.z = __ldg(&x[((b * NC + 4 * g + 2) * NT + t) * HW + hw]);
        v.w = __ldg(&x[((b * NC + 4 * g + 3) * NT + t) * HW + hw]);
        reinterpret_cast<float4*>(g_x4)[tid] = v;
    } else {
        // B fragment pack (verified R9): g_bfrag[tap][split][ntile][lane];
        // lane l: b.x = {B[2(l%4)][n], B[2(l%4)+1][n]}, b.y = {B[+8][n],
        // B[+9][n]}, n = nt*8 + l/4, B[c][co] = w[co][c][tap].
        const int i = (blockIdx.x - 1024) * 256 + threadIdx.x;
        if (i >= NK * 2 * 2 * 32) return;
        const int l  = i & 31;
        const int nt = (i >> 5) & 1;
        const int s  = (i >> 6) & 1;
        const int k  = i >> 7;
        const int n  = nt * 8 + (l >> 2);
        const int kp = (l & 3) * 2;
        __nv_bfloat16 e[4];
#pragma unroll
        for (int j = 0; j < 4; j++) {
            const int c = kp + (j & 1) + (j >> 1) * 8;
            const float v = wgt[(n * NC + c) * NK + k];
            const __nv_bfloat16 hi = __float2bfloat16(v);
            e[j] = s ? __float2bfloat16(v - __bfloat162float(hi)) : hi;
        }
        __nv_bfloat162 r0 = __halves2bfloat162(e[0], e[1]);
        __nv_bfloat162 r1 = __halves2bfloat162(e[2], e[3]);
        uint2 o;
        o.x = *reinterpret_cast<uint32_t*>(&r0);
        o.y = *reinterpret_cast<uint32_t*>(&r1);
        g_bfrag[i] = o;
    }
}

// ---------------------------------------------------------------------------
// per-tap gather + bilinear + bf16 hi/lo split (R9 body, unchanged math)
static __device__ __forceinline__ void gather_tap(
    const ulonglong2* __restrict__ pl, const float* __restrict__ tb,
    int k, int kh, int kw, int h, int w,
    uint32_t hi[8], uint32_t lo[8])
{
    const float offh = __ldg(tb + (2 * k) * THW);
    const float offw = __ldg(tb + (2 * k + 1) * THW);

    const float ph = (float)(h - 1 + kh) + offh;
    const float pw = (float)(w - 1 + kw) + offw;
    const int h0 = __float2int_rd(ph);
    const int w0 = __float2int_rd(pw);
    const float fh = ph - (float)h0;
    const float fw = pw - (float)w0;
    const int h1 = h0 + 1, w1 = w0 + 1;
    const bool vh0 = (h0 >= 0) & (h0 < NH);
    const bool vh1 = (h1 >= 0) & (h1 < NH);
    const bool vw0 = (w0 >= 0) & (w0 < NW);
    const bool vw1 = (w1 >= 0) & (w1 < NW);
    const float gh0 = 1.0f - fh, gw0 = 1.0f - fw;
    const float c00 = (vh0 & vw0) ? gh0 * gw0 : 0.0f;
    const float c01 = (vh0 & vw1) ? gh0 * fw  : 0.0f;
    const float c10 = (vh1 & vw0) ? fh  * gw0 : 0.0f;
    const float c11 = (vh1 & vw1) ? fh  * fw  : 0.0f;
    const int h0c = min(max(h0, 0), NH - 1);
    const int h1c = min(max(h1, 0), NH - 1);
    const int w0c = min(max(w0, 0), NW - 1);
    const int w1c = min(max(w1, 0), NW - 1);
    const int i00 = h0c * NW + w0c;
    const int i01 = h0c * NW + w1c;
    const int i10 = h1c * NW + w0c;
    const int i11 = h1c * NW + w1c;

    unsigned long long cc00, cc01, cc10, cc11;
    PACKB(cc00, c00); PACKB(cc01, c01);
    PACKB(cc10, c10); PACKB(cc11, c11);

#pragma unroll
    for (int g = 0; g < 4; g++) {
        const ulonglong2* __restrict__ pg = pl + g * HW;
        unsigned long long u0 = 0ULL, u1 = 0ULL;
        { const ulonglong2 a = __ldg(pg + i00);
          FMA2(u0, cc00, a.x); FMA2(u1, cc00, a.y); }
        { const ulonglong2 a = __ldg(pg + i01);
          FMA2(u0, cc01, a.x); FMA2(u1, cc01, a.y); }
        { const ulonglong2 a = __ldg(pg + i10);
          FMA2(u0, cc10, a.x); FMA2(u1, cc10, a.y); }
        { const ulonglong2 a = __ldg(pg + i11);
          FMA2(u0, cc11, a.x); FMA2(u1, cc11, a.y); }
        float v0, v1, v2, v3;
        UNPACK2(v0, v1, u0);
        UNPACK2(v2, v3, u1);
        __nv_bfloat162 hA = __floats2bfloat162_rn(v0, v1); // .x = even c
        __nv_bfloat162 hB = __floats2bfloat162_rn(v2, v3);
        float2 fA = __bfloat1622float2(hA);
        float2 fB = __bfloat1622float2(hB);
        __nv_bfloat162 lA = __floats2bfloat162_rn(v0 - fA.x, v1 - fA.y);
        __nv_bfloat162 lB = __floats2bfloat162_rn(v2 - fB.x, v3 - fB.y);
        hi[2 * g]     = *reinterpret_cast<uint32_t*>(&hA);
        hi[2 * g + 1] = *reinterpret_cast<uint32_t*>(&hB);
        lo[2 * g]     = *reinterpret_cast<uint32_t*>(&lA);
        lo[2 * g + 1] = *reinterpret_cast<uint32_t*>(&lB);
    }
}

static __device__ __forceinline__ void sts_tap(
    uint32_t abuf, int lane, const uint32_t hi[8], const uint32_t lo[8])
{
    const uint32_t r = abuf + (uint32_t)lane * 80;
    asm volatile("st.shared.v4.b32 [%0], {%1,%2,%3,%4};"
        :: "r"(r), "r"(hi[0]), "r"(hi[1]), "r"(hi[2]), "r"(hi[3]) : "memory");
    asm volatile("st.shared.v4.b32 [%0], {%1,%2,%3,%4};"
        :: "r"(r + 16), "r"(hi[4]), "r"(hi[5]), "r"(hi[6]), "r"(hi[7]) : "memory");
    asm volatile("st.shared.v4.b32 [%0], {%1,%2,%3,%4};"
        :: "r"(r + 32), "r"(lo[0]), "r"(lo[1]), "r"(lo[2]), "r"(lo[3]) : "memory");
    asm volatile("st.shared.v4.b32 [%0], {%1,%2,%3,%4};"
        :: "r"(r + 48), "r"(lo[4]), "r"(lo[5]), "r"(lo[6]), "r"(lo[7]) : "memory");
}

// B fragments loaded directly from global (L1-resident 27.6KB table)
static __device__ __forceinline__ void mma_tap(
    uint32_t abuf, int k, int lane, float d[2][2][4])
{
    uint32_t ah[2][4], al[2][4];
    const uint32_t r0a = abuf + (uint32_t)(lane & 15) * 80
                       + (uint32_t)(lane >> 4) * 16;
    LDM4(ah[0], r0a);
    LDM4(ah[1], r0a + 16 * 80);
    LDM4(al[0], r0a + 32);
    LDM4(al[1], r0a + 16 * 80 + 32);

    const uint2* __restrict__ bp = g_bfrag + k * 128 + lane;
    const uint2 bh0 = __ldg(bp);
    const uint2 bh1 = __ldg(bp + 32);
    const uint2 bl0 = __ldg(bp + 64);
    const uint2 bl1 = __ldg(bp + 96);

    MMA16816(d[0][0], ah[0], bh0); MMA16816(d[0][1], ah[0], bh1);
    MMA16816(d[1][0], ah[1], bh0); MMA16816(d[1][1], ah[1], bh1);
    MMA16816(d[0][0], al[0], bh0); MMA16816(d[0][1], al[0], bh1);
    MMA16816(d[1][0], al[1], bh0); MMA16816(d[1][1], al[1], bh1);
    MMA16816(d[0][0], ah[0], bl0); MMA16816(d[0][1], ah[0], bl1);
    MMA16816(d[1][0], ah[1], bl0); MMA16816(d[1][1], ah[1], bl1);
}

// ---------------------------------------------------------------------------
// main kernel: ONE WARP PER BLOCK (32 threads), warp = 32 consecutive points.
// 16 blocks/SM resident -> near-perfect load balance across 148 SMs.
// dynamic smem: two 2560B staging buffers.
#define STG_BYTES   2560
#define SMEM_BYTES  (2 * STG_BYTES)   // 5120

__global__ void __launch_bounds__(32, 16)
deform_conv3d_mma_kernel(const float* __restrict__ temp,
                         const float* __restrict__ bias,
                         float* __restrict__ out)
{
    extern __shared__ __align__(16) uint8_t dynsm[];

    const int lane = threadIdx.x;
    const int wpt  = blockIdx.x * 32;   // warp base point
    const int pt   = wpt + lane;
    const int w = pt & 63;
    const int h = (pt >> 6) & 63;
    const int t = (pt >> 12) & 7;   // warp-uniform
    const int b = pt >> 15;         // warp-uniform
    const int sp = pt & (THW - 1);

    const uint32_t abuf0 = smem_u32(dynsm);
    const uint32_t abuf1 = abuf0 + STG_BYTES;
    const float* __restrict__ tb = temp + b * (2 * NK * THW) + sp;
    const ulonglong2* __restrict__ x4all =
        reinterpret_cast<const ulonglong2*>(g_x4) + b * NT * 4 * HW;

    float d[2][2][4];
#pragma unroll
    for (int m = 0; m < 2; m++)
#pragma unroll
        for (int n = 0; n < 2; n++)
#pragma unroll
            for (int j = 0; j < 4; j++) d[m][n][j] = 0.0f;

    for (int kt = 0; kt < 3; kt++) {
        const int ti = t - 1 + kt;
        if (ti < 0 || ti >= NT) continue;            // warp-uniform branch
        const ulonglong2* __restrict__ pl = x4all + ti * 4 * HW;
        const int kb = kt * 9;

        // 4 pipelined pairs + 1 tail tap (R12 structure)
#pragma unroll
        for (int pp = 0; pp < 4; pp++) {
            const int kk0 = 2 * pp;
            const int kk1 = kk0 + 1;
            uint32_t hiA[8], loA[8], hiB[8], loB[8];
            gather_tap(pl, tb, kb + kk0, kk0 / 3, kk0 % 3, h, w, hiA, loA);
            gather_tap(pl, tb, kb + kk1, kk1 / 3, kk1 % 3, h, w, hiB, loB);
            sts_tap(abuf0, lane, hiA, loA);
            sts_tap(abuf1, lane, hiB, loB);
            __syncwarp();                      // RAW for ldmatrix
            mma_tap(abuf0, kb + kk0, lane, d);
            mma_tap(abuf1, kb + kk1, lane, d);
            __syncwarp();                      // WAR before next pair's STS
        }
        {
            uint32_t hiA[8], loA[8];
            gather_tap(pl, tb, kb + 8, 2, 2, h, w, hiA, loA);
            sts_tap(abuf0, lane, hiA, loA);
            __syncwarp();
            mma_tap(abuf0, kb + 8, lane, d);
            __syncwarp();
        }
    }

    // epilogue: D frag (m16n8): lane -> rows {l/4, l/4+8}, cols {2(l%4), +1}
    const int r0 = lane >> 2;
    const int cp = (lane & 3) * 2;
    const float bv[4] = { __ldg(bias + cp),     __ldg(bias + cp + 1),
                          __ldg(bias + cp + 8), __ldg(bias + cp + 9) };
    const int wsp = wpt & (THW - 1);
    float* __restrict__ ob = out + b * (NCO * THW) + wsp;
#pragma unroll
    for (int m = 0; m < 2; m++)
#pragma unroll
        for (int n = 0; n < 2; n++) {
            const int col = n * 8 + cp;
            const int row = 16 * m + r0;
            ob[(col)     * THW + row]     = d[m][n][0] + bv[n * 2 + 0];
            ob[(col + 1) * THW + row]     = d[m][n][1] + bv[n * 2 + 1];
            ob[(col)     * THW + row + 8] = d[m][n][2] + bv[n * 2 + 0];
            ob[(col + 1) * THW + row + 8] = d[m][n][3] + bv[n * 2 + 1];
        }
}

extern "C" void kernel_launch(void* const* d_in, const int* in_sizes, int n_in,
                              void* d_out, int out_size)
{
    const float* x    = (const float*)d_in[0];
    const float* temp = (const float*)d_in[1];
    const float* wgt  = (const float*)d_in[2];
    const float* bias = (const float*)d_in[3];
    float* out = (float*)d_out;

    prep_kernel<<<1024 + 14, 256>>>(x, wgt);
    deform_conv3d_mma_kernel<<<(NB * THW) / 32, 32, SMEM_BYTES>>>(
        temp, bias, out);
}